// round 13
// baseline (speedup 1.0000x reference)
#include <cuda_runtime.h>
#include <cuda_bf16.h>
#include <cstdint>

// ---------------------------------------------------------------------------
// CrossVariateAdapter: B=16, C=1024, NP=512, DM=512, H=8, D=64, TOPK=16
// Outputs concatenated: M_tilde (16*1024*512 fp32) then A (16*1024*1024 fp32)
// Round 13: qk (scalar fma-bound) + vproj (HMMA tensor-bound) merged into one
// launch with 1-in-9 interleave for pipe overlap; streaming cache hints keep
// V resident in L2 for the attn gather. Arithmetic identical to round 12.
// ---------------------------------------------------------------------------

static constexpr size_t PLANE  = 8388608;   // 16384*512
static constexpr size_t WPLANE = 262144;    // 512*512

// split planes (bf16, 3 levels each)
static __device__ __nv_bfloat16 g_Ms[3 * PLANE];
static __device__ __nv_bfloat16 g_Qs[3 * PLANE];
static __device__ __nv_bfloat16 g_Ks[3 * PLANE];
static __device__ __nv_bfloat16 g_Os[3 * PLANE];
static __device__ __nv_bfloat16 g_Wvs[3 * WPLANE];
static __device__ __nv_bfloat16 g_Wos[3 * WPLANE];
// fp32 scratch
static __device__ float g_V[PLANE];
static __device__ float g_S[134217728];     // (B*H, C, C) 512 MB

// ---------------------------------------------------------------------------
// helpers
// ---------------------------------------------------------------------------
__device__ __forceinline__ uint32_t smem_u32(const void* p) {
    uint32_t a;
    asm("{ .reg .u64 t; cvta.to.shared.u64 t, %1; cvt.u32.u64 %0, t; }"
        : "=r"(a) : "l"(p));
    return a;
}
__device__ __forceinline__ uint32_t cvt_bf2(float hi, float lo) {
    uint32_t p;
    asm("cvt.rn.bf16x2.f32 %0, %1, %2;" : "=r"(p) : "f"(hi), "f"(lo));
    return p;
}
__device__ __forceinline__ uint32_t redux_max_u32(uint32_t v) {
    uint32_t r;
    asm volatile("redux.sync.max.u32 %0, %1, 0xffffffff;" : "=r"(r) : "r"(v));
    return r;
}
__device__ __forceinline__ void split_pair_store(__nv_bfloat16* base, size_t plane,
                                                 size_t off, float v0, float v1)
{
    uint32_t p0 = cvt_bf2(v1, v0);
    float r0 = v0 - __uint_as_float(p0 << 16);
    float r1 = v1 - __uint_as_float(p0 & 0xFFFF0000u);
    uint32_t p1 = cvt_bf2(r1, r0);
    float s0 = r0 - __uint_as_float(p1 << 16);
    float s1 = r1 - __uint_as_float(p1 & 0xFFFF0000u);
    uint32_t p2 = cvt_bf2(s1, s0);
    *(uint32_t*)(base + off)             = p0;
    *(uint32_t*)(base + plane + off)     = p1;
    *(uint32_t*)(base + 2 * plane + off) = p2;
}
__device__ __forceinline__ void split_one_store(__nv_bfloat16* base, size_t plane,
                                                size_t off, float v)
{
    __nv_bfloat16 b0 = __float2bfloat16(v);
    float r = v - __bfloat162float(b0);
    __nv_bfloat16 b1 = __float2bfloat16(r);
    float r2 = r - __bfloat162float(b1);
    base[off]             = b0;
    base[plane + off]     = b1;
    base[2 * plane + off] = __float2bfloat16(r2);
}

__device__ __forceinline__ void mma16816(float* c, const uint32_t* a, const uint32_t* b)
{
    asm volatile(
        "mma.sync.aligned.m16n8k16.row.col.f32.bf16.bf16.f32 "
        "{%0,%1,%2,%3}, {%4,%5,%6,%7}, {%8,%9}, {%0,%1,%2,%3};"
        : "+f"(c[0]), "+f"(c[1]), "+f"(c[2]), "+f"(c[3])
        : "r"(a[0]), "r"(a[1]), "r"(a[2]), "r"(a[3]), "r"(b[0]), "r"(b[1]));
}
__device__ __forceinline__ void ldmx4(uint32_t* r, uint32_t addr)
{
    asm volatile("ldmatrix.sync.aligned.m8n8.x4.shared.b16 {%0,%1,%2,%3}, [%4];"
        : "=r"(r[0]), "=r"(r[1]), "=r"(r[2]), "=r"(r[3]) : "r"(addr));
}
__device__ __forceinline__ void ldmx2(uint32_t* r, uint32_t addr)
{
    asm volatile("ldmatrix.sync.aligned.m8n8.x2.shared.b16 {%0,%1}, [%2];"
        : "=r"(r[0]), "=r"(r[1]) : "r"(addr));
}

// ---------------------------------------------------------------------------
// split kernel: fp32 -> 3 bf16 planes (4 floats per thread)
// ---------------------------------------------------------------------------
__global__ void __launch_bounds__(256) split_kernel(
    const float* __restrict__ src, __nv_bfloat16* __restrict__ dst, size_t plane)
{
    size_t i4 = (size_t)blockIdx.x * 256 + threadIdx.x;
    float4 v = ((const float4*)src)[i4];
    split_pair_store(dst, plane, i4 * 4,     v.x, v.y);
    split_pair_store(dst, plane, i4 * 4 + 2, v.z, v.w);
}

// ---------------------------------------------------------------------------
// HMMA mainloop: C(128x128) += A(128xK) * B(128xK)^T via split-bf16.
// 256 threads, 8 warps (2x4), warp tile 64x32, BK=16, double-buffered smem.
// ---------------------------------------------------------------------------
template<int NPROD, int NSPLIT>
__device__ __forceinline__ void gemm_tiles(
    const __nv_bfloat16* __restrict__ A0, const __nv_bfloat16* __restrict__ A1,
    const __nv_bfloat16* __restrict__ A2, const __nv_bfloat16* __restrict__ B0,
    const __nv_bfloat16* __restrict__ B1, const __nv_bfloat16* __restrict__ B2,
    int nchunk, char* sm, float (&acc)[4][4][4])
{
    int t = threadIdx.x, warp = t >> 5, lane = t & 31;
    uint32_t smb = smem_u32(sm);

    int frow = t >> 1, fhalf = t & 1;
    size_t srcoff = (size_t)frow * 512 + fhalf * 8;
    uint32_t fdst = (uint32_t)frow * 32 + (((uint32_t)fhalf << 4) ^ ((frow & 4) << 2));

    int wm = (warp >> 2) << 6;
    int wn = (warp & 3) << 5;
    int tile = lane >> 3, r8 = lane & 7;
    int arow = ((tile & 1) << 3) + r8, ahalf = tile >> 1;
    uint32_t aoff = (uint32_t)(wm + arow) * 32 + (((uint32_t)ahalf << 4) ^ ((arow & 4) << 2));
    int bl = lane & 15, btile = bl >> 3, br = bl & 7;
    uint32_t boff = (uint32_t)(wn + br) * 32 + (((uint32_t)btile << 4) ^ ((br & 4) << 2));

    const __nv_bfloat16* As[3] = {A0 + srcoff, A1 + srcoff, A2 + srcoff};
    const __nv_bfloat16* Bs[3] = {B0 + srcoff, B1 + srcoff, B2 + srcoff};

    uint4 ra[NSPLIT], rb[NSPLIT];
#pragma unroll
    for (int s = 0; s < NSPLIT; s++) {
        ra[s] = *(const uint4*)(As[s]);
        rb[s] = *(const uint4*)(Bs[s]);
    }
#pragma unroll
    for (int s = 0; s < NSPLIT; s++) {
        *(uint4*)(sm + s * 4096 + fdst)       = ra[s];
        *(uint4*)(sm + (3 + s) * 4096 + fdst) = rb[s];
    }
    __syncthreads();

    static const int SA[8] = {0, 0, 1, 1, 0, 2, 1, 2};
    static const int SB[8] = {0, 1, 0, 1, 2, 0, 2, 1};

    for (int i = 0; i < nchunk; i++) {
        uint32_t bufb = (uint32_t)(i & 1) * 24576u;
        bool pf = (i + 1 < nchunk);
        if (pf) {
#pragma unroll
            for (int s = 0; s < NSPLIT; s++) {
                ra[s] = *(const uint4*)(As[s] + (size_t)(i + 1) * 16);
                rb[s] = *(const uint4*)(Bs[s] + (size_t)(i + 1) * 16);
            }
        }

        uint32_t Af[NSPLIT][4][4], Bf[NSPLIT][4][2];
#pragma unroll
        for (int s = 0; s < NSPLIT; s++) {
#pragma unroll
            for (int mt = 0; mt < 4; mt++)
                ldmx4(Af[s][mt], smb + bufb + s * 4096u + mt * 512u + aoff);
#pragma unroll
            for (int nt = 0; nt < 4; nt++)
                ldmx2(Bf[s][nt], smb + bufb + (3 + s) * 4096u + nt * 256u + boff);
        }

#pragma unroll
        for (int p = 0; p < NPROD; p++) {
#pragma unroll
            for (int mt = 0; mt < 4; mt++)
#pragma unroll
                for (int nt = 0; nt < 4; nt++)
                    mma16816(acc[mt][nt], Af[SA[p]][mt], Bf[SB[p]][nt]);
        }

        if (pf) {
            uint32_t ob = (uint32_t)((i + 1) & 1) * 24576u;
#pragma unroll
            for (int s = 0; s < NSPLIT; s++) {
                *(uint4*)(sm + ob + s * 4096 + fdst)       = ra[s];
                *(uint4*)(sm + ob + (3 + s) * 4096 + fdst) = rb[s];
            }
        }
        __syncthreads();
    }
}

// ---------------------------------------------------------------------------
// Kernel 1 (merged): qk scalar GEMM blocks + vproj HMMA blocks, interleaved
// 1-in-9 (512*9 = 4608 blocks). vproj uses the tensor pipe, qk the fma pipe;
// co-residency overlaps them. Dynamic smem 48KB shared by both branches.
// ---------------------------------------------------------------------------
__global__ void __launch_bounds__(256, 2) qkv_merged_kernel(
    const float* __restrict__ Mm, const float* __restrict__ Wq,
    const float* __restrict__ Wk)
{
    extern __shared__ char sm[];
    int bid = blockIdx.x;

    if (bid % 9 == 0) {
        // ---- vproj branch: HMMA split, 3 products. idx 0..511 ----
        int vb = bid / 9;
        int m0 = (vb >> 2) << 7, n0 = (vb & 3) << 7;
        size_t aoff = (size_t)m0 * 512, boff = (size_t)n0 * 512;

        float acc[4][4][4];
#pragma unroll
        for (int a = 0; a < 4; a++)
#pragma unroll
            for (int b = 0; b < 4; b++)
#pragma unroll
                for (int c = 0; c < 4; c++) acc[a][b][c] = 0.f;

        gemm_tiles<3, 2>(g_Ms + aoff, g_Ms + PLANE + aoff, g_Ms + 2 * PLANE + aoff,
                         g_Wvs + boff, g_Wvs + WPLANE + boff, g_Wvs + 2 * WPLANE + boff,
                         32, sm, acc);

        int t = threadIdx.x, warp = t >> 5, lane = t & 31;
        int gq = lane >> 2, tq = lane & 3;
        int wm = (warp >> 2) << 6, wn = (warp & 3) << 5;

#pragma unroll
        for (int mt = 0; mt < 4; mt++)
#pragma unroll
            for (int nt = 0; nt < 4; nt++) {
                int row = m0 + wm + mt * 16 + gq;
                int col = n0 + wn + nt * 8 + 2 * tq;
                *(float2*)(g_V + (size_t)row * 512 + col) =
                    make_float2(acc[mt][nt][0], acc[mt][nt][1]);
                *(float2*)(g_V + (size_t)(row + 8) * 512 + col) =
                    make_float2(acc[mt][nt][2], acc[mt][nt][3]);
            }
    } else {
        // ---- qk branch: fp32 scalar (exact) + split-store epilogue ----
        int q = bid - bid / 9 - 1;          // 0..4095
        int z = q >> 11;                    // 0: Q, 1: K
        int r = q & 2047;
        int m0 = (r >> 3) << 6;
        int n0 = (r & 7) << 6;

        float (*As)[68] = (float(*)[68])sm;
        float (*Bs)[68] = (float(*)[68])(sm + 16 * 68 * sizeof(float));

        const float* W     = (z == 0) ? Wq  : Wk;
        __nv_bfloat16* dst = (z == 0) ? g_Qs : g_Ks;

        int t  = threadIdx.x;
        int tx = t & 15, ty = t >> 4;
        int lr = t >> 2, lk = (t & 3) << 2;

        float acc[4][4];
#pragma unroll
        for (int u = 0; u < 4; u++)
#pragma unroll
            for (int v = 0; v < 4; v++) acc[u][v] = 0.f;

        const float* Ap = Mm + (size_t)(m0 + lr) * 512 + lk;
        const float* Bp = W  + (size_t)(n0 + lr) * 512 + lk;

        for (int k0 = 0; k0 < 512; k0 += 16) {
            float4 av = *(const float4*)(Ap + k0);
            float4 bv = *(const float4*)(Bp + k0);
            As[lk + 0][lr] = av.x; As[lk + 1][lr] = av.y;
            As[lk + 2][lr] = av.z; As[lk + 3][lr] = av.w;
            Bs[lk + 0][lr] = bv.x; Bs[lk + 1][lr] = bv.y;
            Bs[lk + 2][lr] = bv.z; Bs[lk + 3][lr] = bv.w;
            __syncthreads();
#pragma unroll
            for (int k = 0; k < 16; k++) {
                float4 a = *(const float4*)&As[k][ty << 2];
                float4 b = *(const float4*)&Bs[k][tx << 2];
                float a4[4] = {a.x, a.y, a.z, a.w};
                float b4[4] = {b.x, b.y, b.z, b.w};
#pragma unroll
                for (int u = 0; u < 4; u++)
#pragma unroll
                    for (int v = 0; v < 4; v++) acc[u][v] += a4[u] * b4[v];
            }
            __syncthreads();
        }

        int n = n0 + (tx << 2);
#pragma unroll
        for (int u = 0; u < 4; u++) {
            int m = m0 + (ty << 2) + u;
            size_t off = (size_t)m * 512 + n;
            split_pair_store(dst, PLANE, off,     acc[u][0], acc[u][1]);
            split_pair_store(dst, PLANE, off + 2, acc[u][2], acc[u][3]);
        }
    }
}

// ---------------------------------------------------------------------------
// Kernel 3: scores via HMMA split, 6 products (exact-split fp32 Q/K inputs).
// grid (8, 8, 128). S stores use streaming hint (read-once buffer).
// ---------------------------------------------------------------------------
__global__ void __launch_bounds__(256) scores_kernel()
{
    extern __shared__ char sm[];
    int z = blockIdx.z, b = z >> 3, h = z & 7;
    int m0 = blockIdx.x << 7, n0 = blockIdx.y << 7;

    size_t aoff = (size_t)((b << 10) + m0) * 512 + (h << 6);
    size_t boff = (size_t)((b << 10) + n0) * 512 + (h << 6);

    float acc[4][4][4];
#pragma unroll
    for (int a = 0; a < 4; a++)
#pragma unroll
        for (int c = 0; c < 4; c++)
#pragma unroll
            for (int d = 0; d < 4; d++) acc[a][c][d] = 0.f;

    gemm_tiles<6, 3>(g_Qs + aoff, g_Qs + PLANE + aoff, g_Qs + 2 * PLANE + aoff,
                     g_Ks + boff, g_Ks + PLANE + boff, g_Ks + 2 * PLANE + boff,
                     4, sm, acc);

    int t = threadIdx.x, warp = t >> 5, lane = t & 31;
    int gq = lane >> 2, tq = lane & 3;
    int wm = (warp >> 2) << 6, wn = (warp & 3) << 5;
    float* Sz = g_S + ((size_t)z << 20);
    const float sc = 0.125f;

#pragma unroll
    for (int mt = 0; mt < 4; mt++)
#pragma unroll
        for (int nt = 0; nt < 4; nt++) {
            int row = m0 + wm + mt * 16 + gq;
            int col = n0 + wn + nt * 8 + 2 * tq;
            __stcs((float2*)(Sz + (size_t)row * 1024 + col),
                   make_float2(acc[mt][nt][0] * sc, acc[mt][nt][1] * sc));
            __stcs((float2*)(Sz + (size_t)(row + 8) * 1024 + col),
                   make_float2(acc[mt][nt][2] * sc, acc[mt][nt][3] * sc));
        }
}

// ---------------------------------------------------------------------------
// Kernel 4: attention top-16/softmax/AV + A mask. 288 thr = 9 warps.
// S loads use streaming hint (read-once) so V stays L2-resident.
// ---------------------------------------------------------------------------
__device__ __forceinline__ unsigned fkey(float f) {
    unsigned u = __float_as_uint(f);
    return (u & 0x80000000u) ? ~u : (u | 0x80000000u);
}
__device__ __forceinline__ float unkey(unsigned hu) {
    return (hu & 0x80000000u) ? __uint_as_float(hu & 0x7FFFFFFFu)
                              : __uint_as_float(~hu);
}

__global__ void __launch_bounds__(288) attn_kernel(float* __restrict__ dout)
{
    __shared__ float s_rows[9][1024];

    int t = threadIdx.x, w = t >> 5, lane = t & 31;
    int bi = blockIdx.x;                  // 0..16383
    int b  = bi >> 10, i = bi & 1023;

    float* Arow = dout + 8388608 + (size_t)bi * 1024;

    if (w < 8) {
        const float4* r4 = (const float4*)(g_S +
            ((size_t)((b << 3) + w) * 1024 + i) * 1024);
#pragma unroll
        for (int q = 0; q < 8; q++)
            *(float4*)&s_rows[w][(lane << 2) + (q << 7)] = __ldcs(r4 + lane + (q << 5));
    } else {
#pragma unroll
        for (int q = 0; q < 8; q++)
            ((float4*)Arow)[lane + (q << 5)] = make_float4(0.f, 0.f, 0.f, 0.f);
    }
    __syncthreads();

    if (w == 8) {
#pragma unroll
        for (int q = 0; q < 8; q++) {
            int o = (lane << 2) + (q << 7);
            float ax = 0.f, ay = 0.f, az = 0.f, aw2 = 0.f;
#pragma unroll
            for (int h = 0; h < 8; h++) {
                float4 x = *(const float4*)&s_rows[h][o];
                ax += x.x; ay += x.y; az += x.z; aw2 += x.w;
            }
            *(float4*)&s_rows[8][o] = make_float4(ax * 0.125f, ay * 0.125f,
                                                  az * 0.125f, aw2 * 0.125f);
        }
    }

    const float* row = s_rows[w];
    const int jbase = lane << 2;

    unsigned long long best = 0ull, second = 0ull;
    unsigned taken = 0u;
#pragma unroll
    for (int q = 0; q < 8; q++) {
        float4 x = *(const float4*)&row[jbase + (q << 7)];
        float xv[4] = {x.x, x.y, x.z, x.w};
#pragma unroll
        for (int e = 0; e < 4; e++) {
            int j = jbase + (q << 7) + e;
            unsigned long long key =
                ((unsigned long long)fkey(xv[e]) << 32) | (unsigned)(1023 - j);
            if (key > best) { second = best; best = key; }
            else if (key > second) { second = key; }
        }
    }

    float selv = 0.f;
    int   selj = 0;
#pragma unroll 1
    for (int it = 0; it < 16; it++) {
        uint32_t myhi = (uint32_t)(best >> 32);
        uint32_t mylo = (uint32_t)best;
        uint32_t m  = redux_max_u32(myhi);
        uint32_t jl = (myhi == m) ? mylo : 0u;
        uint32_t mj = redux_max_u32(jl);
        if (myhi == m && mylo == mj) {
            int jw  = 1023 - (int)mj;
            int kkw = ((jw >> 7) << 2) | (jw & 3);
            taken |= 1u << kkw;
            if (second) { best = second; second = 0ull; }
            else {
                best = 0ull; second = 0ull;
#pragma unroll
                for (int kk = 0; kk < 32; kk++) {
                    if (taken & (1u << kk)) continue;
                    int j = jbase + ((kk >> 2) << 7) + (kk & 3);
                    unsigned long long key =
                        ((unsigned long long)fkey(row[j]) << 32) | (unsigned)(1023 - j);
                    if (key > best) { second = best; best = key; }
                    else if (key > second) { second = key; }
                }
            }
        }
        if (lane == it) { selv = unkey(m); selj = 1023 - (int)mj; }
    }

    if (w < 8) {
        float mx = __shfl_sync(0xFFFFFFFFu, selv, 0);
        float e  = (lane < 16) ? __expf(selv - mx) : 0.f;
        float ss = e;
#pragma unroll
        for (int off = 16; off > 0; off >>= 1)
            ss += __shfl_xor_sync(0xFFFFFFFFu, ss, off);
        float aw = e / ss;

        const float* Vb = g_V + ((size_t)(b << 10)) * 512 + (w << 6);
        float o0 = 0.f, o1 = 0.f;
#pragma unroll
        for (int it2 = 0; it2 < 16; it2++) {
            int   jb = __shfl_sync(0xFFFFFFFFu, selj, it2);
            float ab = __shfl_sync(0xFFFFFFFFu, aw, it2);
            const float* vr = Vb + (size_t)jb * 512;
            o0 += ab * vr[lane];
            o1 += ab * vr[lane + 32];
        }
        size_t orow = (size_t)bi * 512 + (w << 6);
        split_one_store(g_Os, PLANE, orow + lane,      o0);
        split_one_store(g_Os, PLANE, orow + lane + 32, o1);
    } else {
        if (lane < 16) Arow[selj] = 1.0f;
    }
}

// ---------------------------------------------------------------------------
// Kernel 5: delta = O @ Wo^T + bo;  M_tilde = M + gate*delta (HMMA, 3 prod).
// ---------------------------------------------------------------------------
__global__ void __launch_bounds__(256) proj_kernel(
    const float* __restrict__ Mm, const float* __restrict__ bo,
    const float* __restrict__ gate, float* __restrict__ dout)
{
    extern __shared__ char sm[];
    int m0 = blockIdx.x << 7, n0 = blockIdx.y << 7;
    size_t aoff = (size_t)m0 * 512, boff = (size_t)n0 * 512;

    float acc[4][4][4];
#pragma unroll
    for (int a = 0; a < 4; a++)
#pragma unroll
        for (int b = 0; b < 4; b++)
#pragma unroll
            for (int c = 0; c < 4; c++) acc[a][b][c] = 0.f;

    gemm_tiles<3, 2>(g_Os + aoff, g_Os + PLANE + aoff, g_Os + 2 * PLANE + aoff,
                     g_Wos + boff, g_Wos + WPLANE + boff, g_Wos + 2 * WPLANE + boff,
                     32, sm, acc);

    int t = threadIdx.x, warp = t >> 5, lane = t & 31;
    int gq = lane >> 2, tq = lane & 3;
    int wm = (warp >> 2) << 6, wn = (warp & 3) << 5;
    float gg = gate[0];

#pragma unroll
    for (int mt = 0; mt < 4; mt++)
#pragma unroll
        for (int nt = 0; nt < 4; nt++) {
            int col = n0 + wn + nt * 8 + 2 * tq;
            float2 bv = *(const float2*)(bo + col);
#pragma unroll
            for (int hh = 0; hh < 2; hh++) {
                int row = m0 + wm + mt * 16 + gq + hh * 8;
                float2 mv = *(const float2*)(Mm + (size_t)row * 512 + col);
                *(float2*)(dout + (size_t)row * 512 + col) = make_float2(
                    mv.x + gg * (acc[mt][nt][2*hh]   + bv.x),
                    mv.y + gg * (acc[mt][nt][2*hh+1] + bv.y));
            }
        }
}

// ---------------------------------------------------------------------------
extern "C" void kernel_launch(void* const* d_in, const int* in_sizes, int n_in,
                              void* d_out, int out_size)
{
    const float* Mm   = (const float*)d_in[0];
    const float* Wq   = (const float*)d_in[1];
    const float* Wk   = (const float*)d_in[2];
    const float* Wv   = (const float*)d_in[3];
    const float* Wo   = (const float*)d_in[4];
    const float* bo   = (const float*)d_in[5];
    const float* gate = (const float*)d_in[6];
    float* out = (float*)d_out;

    // resolve device-symbol addresses (host-side, capture-safe)
    __nv_bfloat16 *pMs, *pWvs, *pWos;
    cudaGetSymbolAddress((void**)&pMs,  g_Ms);
    cudaGetSymbolAddress((void**)&pWvs, g_Wvs);
    cudaGetSymbolAddress((void**)&pWos, g_Wos);

    split_kernel<<<8192, 256>>>(Mm, pMs, PLANE);
    split_kernel<<<256, 256>>>(Wv, pWvs, WPLANE);
    split_kernel<<<256, 256>>>(Wo, pWos, WPLANE);

    qkv_merged_kernel<<<4608, 256, 49152>>>(Mm, Wq, Wk);
    scores_kernel<<<dim3(8, 8, 128), 256, 49152>>>();
    attn_kernel<<<16384, 288>>>(out);
    proj_kernel<<<dim3(128, 4), 256, 49152>>>(Mm, bo, gate, out);
}

// round 17
// speedup vs baseline: 1.0538x; 1.0538x over previous
#include <cuda_runtime.h>
#include <cuda_bf16.h>
#include <cstdint>

// ---------------------------------------------------------------------------
// CrossVariateAdapter: B=16, C=1024, NP=512, DM=512, H=8, D=64, TOPK=16
// Outputs concatenated: M_tilde (16*1024*512 fp32) then A (16*1024*1024 fp32)
// Round 17: single-stream restore of the round-12 config + cache hints +
// dead-plane elimination (2-level splits where only 2 levels are consumed).
// ---------------------------------------------------------------------------

static constexpr size_t PLANE  = 8388608;   // 16384*512
static constexpr size_t WPLANE = 262144;    // 512*512

// split planes (bf16). Qs/Ks: 3 levels (scores uses 3). Ms/Os/Wvs/Wos: only
// 2 levels are ever read (gemm_tiles<3,2>), so only 2 are written.
static __device__ __nv_bfloat16 g_Ms[3 * PLANE];
static __device__ __nv_bfloat16 g_Qs[3 * PLANE];
static __device__ __nv_bfloat16 g_Ks[3 * PLANE];
static __device__ __nv_bfloat16 g_Os[3 * PLANE];
static __device__ __nv_bfloat16 g_Wvs[3 * WPLANE];
static __device__ __nv_bfloat16 g_Wos[3 * WPLANE];
// fp32 scratch
static __device__ float g_V[PLANE];
static __device__ float g_S[134217728];     // (B*H, C, C) 512 MB

// ---------------------------------------------------------------------------
// helpers
// ---------------------------------------------------------------------------
__device__ __forceinline__ uint32_t smem_u32(const void* p) {
    uint32_t a;
    asm("{ .reg .u64 t; cvta.to.shared.u64 t, %1; cvt.u32.u64 %0, t; }"
        : "=r"(a) : "l"(p));
    return a;
}
__device__ __forceinline__ uint32_t cvt_bf2(float hi, float lo) {
    uint32_t p;
    asm("cvt.rn.bf16x2.f32 %0, %1, %2;" : "=r"(p) : "f"(hi), "f"(lo));
    return p;
}
__device__ __forceinline__ uint32_t redux_max_u32(uint32_t v) {
    uint32_t r;
    asm volatile("redux.sync.max.u32 %0, %1, 0xffffffff;" : "=r"(r) : "r"(v));
    return r;
}
// 3-level exact split (for Q/K planes feeding the 6-product scores GEMM)
__device__ __forceinline__ void split_pair_store3(__nv_bfloat16* base, size_t plane,
                                                  size_t off, float v0, float v1)
{
    uint32_t p0 = cvt_bf2(v1, v0);
    float r0 = v0 - __uint_as_float(p0 << 16);
    float r1 = v1 - __uint_as_float(p0 & 0xFFFF0000u);
    uint32_t p1 = cvt_bf2(r1, r0);
    float s0 = r0 - __uint_as_float(p1 << 16);
    float s1 = r1 - __uint_as_float(p1 & 0xFFFF0000u);
    uint32_t p2 = cvt_bf2(s1, s0);
    *(uint32_t*)(base + off)             = p0;
    *(uint32_t*)(base + plane + off)     = p1;
    *(uint32_t*)(base + 2 * plane + off) = p2;
}
// 2-level split (for operands consumed by gemm_tiles<3,2> only)
__device__ __forceinline__ void split_pair_store2(__nv_bfloat16* base, size_t plane,
                                                  size_t off, float v0, float v1)
{
    uint32_t p0 = cvt_bf2(v1, v0);
    float r0 = v0 - __uint_as_float(p0 << 16);
    float r1 = v1 - __uint_as_float(p0 & 0xFFFF0000u);
    uint32_t p1 = cvt_bf2(r1, r0);
    *(uint32_t*)(base + off)         = p0;
    *(uint32_t*)(base + plane + off) = p1;
}
__device__ __forceinline__ void split_one_store2(__nv_bfloat16* base, size_t plane,
                                                 size_t off, float v)
{
    __nv_bfloat16 b0 = __float2bfloat16(v);
    float r = v - __bfloat162float(b0);
    base[off]         = b0;
    base[plane + off] = __float2bfloat16(r);
}

__device__ __forceinline__ void mma16816(float* c, const uint32_t* a, const uint32_t* b)
{
    asm volatile(
        "mma.sync.aligned.m16n8k16.row.col.f32.bf16.bf16.f32 "
        "{%0,%1,%2,%3}, {%4,%5,%6,%7}, {%8,%9}, {%0,%1,%2,%3};"
        : "+f"(c[0]), "+f"(c[1]), "+f"(c[2]), "+f"(c[3])
        : "r"(a[0]), "r"(a[1]), "r"(a[2]), "r"(a[3]), "r"(b[0]), "r"(b[1]));
}
__device__ __forceinline__ void ldmx4(uint32_t* r, uint32_t addr)
{
    asm volatile("ldmatrix.sync.aligned.m8n8.x4.shared.b16 {%0,%1,%2,%3}, [%4];"
        : "=r"(r[0]), "=r"(r[1]), "=r"(r[2]), "=r"(r[3]) : "r"(addr));
}
__device__ __forceinline__ void ldmx2(uint32_t* r, uint32_t addr)
{
    asm volatile("ldmatrix.sync.aligned.m8n8.x2.shared.b16 {%0,%1}, [%2];"
        : "=r"(r[0]), "=r"(r[1]) : "r"(addr));
}

// ---------------------------------------------------------------------------
// split kernel (2-level): fp32 -> 2 bf16 planes (4 floats per thread)
// ---------------------------------------------------------------------------
__global__ void __launch_bounds__(256) split2_kernel(
    const float* __restrict__ src, __nv_bfloat16* __restrict__ dst, size_t plane)
{
    size_t i4 = (size_t)blockIdx.x * 256 + threadIdx.x;
    float4 v = ((const float4*)src)[i4];
    split_pair_store2(dst, plane, i4 * 4,     v.x, v.y);
    split_pair_store2(dst, plane, i4 * 4 + 2, v.z, v.w);
}

// ---------------------------------------------------------------------------
// HMMA mainloop: C(128x128) += A(128xK) * B(128xK)^T via split-bf16.
// 256 threads, 8 warps (2x4), warp tile 64x32, BK=16, double-buffered smem.
// ---------------------------------------------------------------------------
template<int NPROD, int NSPLIT>
__device__ __forceinline__ void gemm_tiles(
    const __nv_bfloat16* __restrict__ A0, const __nv_bfloat16* __restrict__ A1,
    const __nv_bfloat16* __restrict__ A2, const __nv_bfloat16* __restrict__ B0,
    const __nv_bfloat16* __restrict__ B1, const __nv_bfloat16* __restrict__ B2,
    int nchunk, char* sm, float (&acc)[4][4][4])
{
    int t = threadIdx.x, warp = t >> 5, lane = t & 31;
    uint32_t smb = smem_u32(sm);

    int frow = t >> 1, fhalf = t & 1;
    size_t srcoff = (size_t)frow * 512 + fhalf * 8;
    uint32_t fdst = (uint32_t)frow * 32 + (((uint32_t)fhalf << 4) ^ ((frow & 4) << 2));

    int wm = (warp >> 2) << 6;
    int wn = (warp & 3) << 5;
    int tile = lane >> 3, r8 = lane & 7;
    int arow = ((tile & 1) << 3) + r8, ahalf = tile >> 1;
    uint32_t aoff = (uint32_t)(wm + arow) * 32 + (((uint32_t)ahalf << 4) ^ ((arow & 4) << 2));
    int bl = lane & 15, btile = bl >> 3, br = bl & 7;
    uint32_t boff = (uint32_t)(wn + br) * 32 + (((uint32_t)btile << 4) ^ ((br & 4) << 2));

    const __nv_bfloat16* As[3] = {A0 + srcoff, A1 + srcoff, A2 + srcoff};
    const __nv_bfloat16* Bs[3] = {B0 + srcoff, B1 + srcoff, B2 + srcoff};

    uint4 ra[NSPLIT], rb[NSPLIT];
#pragma unroll
    for (int s = 0; s < NSPLIT; s++) {
        ra[s] = *(const uint4*)(As[s]);
        rb[s] = *(const uint4*)(Bs[s]);
    }
#pragma unroll
    for (int s = 0; s < NSPLIT; s++) {
        *(uint4*)(sm + s * 4096 + fdst)       = ra[s];
        *(uint4*)(sm + (3 + s) * 4096 + fdst) = rb[s];
    }
    __syncthreads();

    static const int SA[8] = {0, 0, 1, 1, 0, 2, 1, 2};
    static const int SB[8] = {0, 1, 0, 1, 2, 0, 2, 1};

    for (int i = 0; i < nchunk; i++) {
        uint32_t bufb = (uint32_t)(i & 1) * 24576u;
        bool pf = (i + 1 < nchunk);
        if (pf) {
#pragma unroll
            for (int s = 0; s < NSPLIT; s++) {
                ra[s] = *(const uint4*)(As[s] + (size_t)(i + 1) * 16);
                rb[s] = *(const uint4*)(Bs[s] + (size_t)(i + 1) * 16);
            }
        }

        uint32_t Af[NSPLIT][4][4], Bf[NSPLIT][4][2];
#pragma unroll
        for (int s = 0; s < NSPLIT; s++) {
#pragma unroll
            for (int mt = 0; mt < 4; mt++)
                ldmx4(Af[s][mt], smb + bufb + s * 4096u + mt * 512u + aoff);
#pragma unroll
            for (int nt = 0; nt < 4; nt++)
                ldmx2(Bf[s][nt], smb + bufb + (3 + s) * 4096u + nt * 256u + boff);
        }

#pragma unroll
        for (int p = 0; p < NPROD; p++) {
#pragma unroll
            for (int mt = 0; mt < 4; mt++)
#pragma unroll
                for (int nt = 0; nt < 4; nt++)
                    mma16816(acc[mt][nt], Af[SA[p]][mt], Bf[SB[p]][nt]);
        }

        if (pf) {
            uint32_t ob = (uint32_t)((i + 1) & 1) * 24576u;
#pragma unroll
            for (int s = 0; s < NSPLIT; s++) {
                *(uint4*)(sm + ob + s * 4096 + fdst)       = ra[s];
                *(uint4*)(sm + ob + (3 + s) * 4096 + fdst) = rb[s];
            }
        }
        __syncthreads();
    }
}

// ---------------------------------------------------------------------------
// Kernel 1: Q,K projections, fp32 scalar (exact), epilogue split-stores (3-lvl).
// ---------------------------------------------------------------------------
__global__ void __launch_bounds__(256) qk_kernel(
    const float* __restrict__ Mm, const float* __restrict__ Wq,
    const float* __restrict__ Wk)
{
    __shared__ float As[16][68];
    __shared__ float Bs[16][68];

    const float* W      = (blockIdx.z == 0) ? Wq  : Wk;
    __nv_bfloat16* dst  = (blockIdx.z == 0) ? g_Qs : g_Ks;

    int t  = threadIdx.x;
    int m0 = blockIdx.x << 6;
    int n0 = blockIdx.y << 6;
    int tx = t & 15, ty = t >> 4;
    int lr = t >> 2, lk = (t & 3) << 2;

    float acc[4][4];
#pragma unroll
    for (int u = 0; u < 4; u++)
#pragma unroll
        for (int v = 0; v < 4; v++) acc[u][v] = 0.f;

    const float* Ap = Mm + (size_t)(m0 + lr) * 512 + lk;
    const float* Bp = W  + (size_t)(n0 + lr) * 512 + lk;

    for (int k0 = 0; k0 < 512; k0 += 16) {
        float4 av = *(const float4*)(Ap + k0);
        float4 bv = *(const float4*)(Bp + k0);
        As[lk + 0][lr] = av.x; As[lk + 1][lr] = av.y;
        As[lk + 2][lr] = av.z; As[lk + 3][lr] = av.w;
        Bs[lk + 0][lr] = bv.x; Bs[lk + 1][lr] = bv.y;
        Bs[lk + 2][lr] = bv.z; Bs[lk + 3][lr] = bv.w;
        __syncthreads();
#pragma unroll
        for (int k = 0; k < 16; k++) {
            float4 a = *(const float4*)&As[k][ty << 2];
            float4 b = *(const float4*)&Bs[k][tx << 2];
            float a4[4] = {a.x, a.y, a.z, a.w};
            float b4[4] = {b.x, b.y, b.z, b.w};
#pragma unroll
            for (int u = 0; u < 4; u++)
#pragma unroll
                for (int v = 0; v < 4; v++) acc[u][v] += a4[u] * b4[v];
        }
        __syncthreads();
    }

    int n = n0 + (tx << 2);
#pragma unroll
    for (int u = 0; u < 4; u++) {
        int m = m0 + (ty << 2) + u;
        size_t off = (size_t)m * 512 + n;
        split_pair_store3(dst, PLANE, off,     acc[u][0], acc[u][1]);
        split_pair_store3(dst, PLANE, off + 2, acc[u][2], acc[u][3]);
    }
}

// ---------------------------------------------------------------------------
// Kernel 2: V projection via HMMA split, 3 products. grid (128, 4).
// ---------------------------------------------------------------------------
__global__ void __launch_bounds__(256) vproj_kernel()
{
    extern __shared__ char sm[];
    int m0 = blockIdx.x << 7, n0 = blockIdx.y << 7;
    size_t aoff = (size_t)m0 * 512, boff = (size_t)n0 * 512;

    float acc[4][4][4];
#pragma unroll
    for (int a = 0; a < 4; a++)
#pragma unroll
        for (int b = 0; b < 4; b++)
#pragma unroll
            for (int c = 0; c < 4; c++) acc[a][b][c] = 0.f;

    gemm_tiles<3, 2>(g_Ms + aoff, g_Ms + PLANE + aoff, g_Ms + 2 * PLANE + aoff,
                     g_Wvs + boff, g_Wvs + WPLANE + boff, g_Wvs + 2 * WPLANE + boff,
                     32, sm, acc);

    int t = threadIdx.x, warp = t >> 5, lane = t & 31;
    int gq = lane >> 2, tq = lane & 3;
    int wm = (warp >> 2) << 6, wn = (warp & 3) << 5;

#pragma unroll
    for (int mt = 0; mt < 4; mt++)
#pragma unroll
        for (int nt = 0; nt < 4; nt++) {
            int row = m0 + wm + mt * 16 + gq;
            int col = n0 + wn + nt * 8 + 2 * tq;
            *(float2*)(g_V + (size_t)row * 512 + col) =
                make_float2(acc[mt][nt][0], acc[mt][nt][1]);
            *(float2*)(g_V + (size_t)(row + 8) * 512 + col) =
                make_float2(acc[mt][nt][2], acc[mt][nt][3]);
        }
}

// ---------------------------------------------------------------------------
// Kernel 3: scores via HMMA split, 6 products. grid (8, 8, 128).
// S stores use streaming hint (read-once buffer).
// ---------------------------------------------------------------------------
__global__ void __launch_bounds__(256) scores_kernel()
{
    extern __shared__ char sm[];
    int z = blockIdx.z, b = z >> 3, h = z & 7;
    int m0 = blockIdx.x << 7, n0 = blockIdx.y << 7;

    size_t aoff = (size_t)((b << 10) + m0) * 512 + (h << 6);
    size_t boff = (size_t)((b << 10) + n0) * 512 + (h << 6);

    float acc[4][4][4];
#pragma unroll
    for (int a = 0; a < 4; a++)
#pragma unroll
        for (int c = 0; c < 4; c++)
#pragma unroll
            for (int d = 0; d < 4; d++) acc[a][c][d] = 0.f;

    gemm_tiles<6, 3>(g_Qs + aoff, g_Qs + PLANE + aoff, g_Qs + 2 * PLANE + aoff,
                     g_Ks + boff, g_Ks + PLANE + boff, g_Ks + 2 * PLANE + boff,
                     4, sm, acc);

    int t = threadIdx.x, warp = t >> 5, lane = t & 31;
    int gq = lane >> 2, tq = lane & 3;
    int wm = (warp >> 2) << 6, wn = (warp & 3) << 5;
    float* Sz = g_S + ((size_t)z << 20);
    const float sc = 0.125f;

#pragma unroll
    for (int mt = 0; mt < 4; mt++)
#pragma unroll
        for (int nt = 0; nt < 4; nt++) {
            int row = m0 + wm + mt * 16 + gq;
            int col = n0 + wn + nt * 8 + 2 * tq;
            __stcs((float2*)(Sz + (size_t)row * 1024 + col),
                   make_float2(acc[mt][nt][0] * sc, acc[mt][nt][1] * sc));
            __stcs((float2*)(Sz + (size_t)(row + 8) * 1024 + col),
                   make_float2(acc[mt][nt][2] * sc, acc[mt][nt][3] * sc));
        }
}

// ---------------------------------------------------------------------------
// Kernel 4: attention top-16/softmax/AV + A mask. 288 thr = 9 warps.
// S loads streaming (read-once) so V stays L2-resident. O stored as 2-level
// split (proj consumes only 2 levels).
// ---------------------------------------------------------------------------
__device__ __forceinline__ unsigned fkey(float f) {
    unsigned u = __float_as_uint(f);
    return (u & 0x80000000u) ? ~u : (u | 0x80000000u);
}
__device__ __forceinline__ float unkey(unsigned hu) {
    return (hu & 0x80000000u) ? __uint_as_float(hu & 0x7FFFFFFFu)
                              : __uint_as_float(~hu);
}

__global__ void __launch_bounds__(288) attn_kernel(float* __restrict__ dout)
{
    __shared__ float s_rows[9][1024];

    int t = threadIdx.x, w = t >> 5, lane = t & 31;
    int bi = blockIdx.x;                  // 0..16383
    int b  = bi >> 10, i = bi & 1023;

    float* Arow = dout + 8388608 + (size_t)bi * 1024;

    if (w < 8) {
        const float4* r4 = (const float4*)(g_S +
            ((size_t)((b << 3) + w) * 1024 + i) * 1024);
#pragma unroll
        for (int q = 0; q < 8; q++)
            *(float4*)&s_rows[w][(lane << 2) + (q << 7)] = __ldcs(r4 + lane + (q << 5));
    } else {
#pragma unroll
        for (int q = 0; q < 8; q++)
            ((float4*)Arow)[lane + (q << 5)] = make_float4(0.f, 0.f, 0.f, 0.f);
    }
    __syncthreads();

    if (w == 8) {
#pragma unroll
        for (int q = 0; q < 8; q++) {
            int o = (lane << 2) + (q << 7);
            float ax = 0.f, ay = 0.f, az = 0.f, aw2 = 0.f;
#pragma unroll
            for (int h = 0; h < 8; h++) {
                float4 x = *(const float4*)&s_rows[h][o];
                ax += x.x; ay += x.y; az += x.z; aw2 += x.w;
            }
            *(float4*)&s_rows[8][o] = make_float4(ax * 0.125f, ay * 0.125f,
                                                  az * 0.125f, aw2 * 0.125f);
        }
    }

    const float* row = s_rows[w];
    const int jbase = lane << 2;

    unsigned long long best = 0ull, second = 0ull;
    unsigned taken = 0u;
#pragma unroll
    for (int q = 0; q < 8; q++) {
        float4 x = *(const float4*)&row[jbase + (q << 7)];
        float xv[4] = {x.x, x.y, x.z, x.w};
#pragma unroll
        for (int e = 0; e < 4; e++) {
            int j = jbase + (q << 7) + e;
            unsigned long long key =
                ((unsigned long long)fkey(xv[e]) << 32) | (unsigned)(1023 - j);
            if (key > best) { second = best; best = key; }
            else if (key > second) { second = key; }
        }
    }

    float selv = 0.f;
    int   selj = 0;
#pragma unroll 1
    for (int it = 0; it < 16; it++) {
        uint32_t myhi = (uint32_t)(best >> 32);
        uint32_t mylo = (uint32_t)best;
        uint32_t m  = redux_max_u32(myhi);
        uint32_t jl = (myhi == m) ? mylo : 0u;
        uint32_t mj = redux_max_u32(jl);
        if (myhi == m && mylo == mj) {
            int jw  = 1023 - (int)mj;
            int kkw = ((jw >> 7) << 2) | (jw & 3);
            taken |= 1u << kkw;
            if (second) { best = second; second = 0ull; }
            else {
                best = 0ull; second = 0ull;
#pragma unroll
                for (int kk = 0; kk < 32; kk++) {
                    if (taken & (1u << kk)) continue;
                    int j = jbase + ((kk >> 2) << 7) + (kk & 3);
                    unsigned long long key =
                        ((unsigned long long)fkey(row[j]) << 32) | (unsigned)(1023 - j);
                    if (key > best) { second = best; best = key; }
                    else if (key > second) { second = key; }
                }
            }
        }
        if (lane == it) { selv = unkey(m); selj = 1023 - (int)mj; }
    }

    if (w < 8) {
        float mx = __shfl_sync(0xFFFFFFFFu, selv, 0);
        float e  = (lane < 16) ? __expf(selv - mx) : 0.f;
        float ss = e;
#pragma unroll
        for (int off = 16; off > 0; off >>= 1)
            ss += __shfl_xor_sync(0xFFFFFFFFu, ss, off);
        float aw = e / ss;

        const float* Vb = g_V + ((size_t)(b << 10)) * 512 + (w << 6);
        float o0 = 0.f, o1 = 0.f;
#pragma unroll
        for (int it2 = 0; it2 < 16; it2++) {
            int   jb = __shfl_sync(0xFFFFFFFFu, selj, it2);
            float ab = __shfl_sync(0xFFFFFFFFu, aw, it2);
            const float* vr = Vb + (size_t)jb * 512;
            o0 += ab * vr[lane];
            o1 += ab * vr[lane + 32];
        }
        size_t orow = (size_t)bi * 512 + (w << 6);
        split_one_store2(g_Os, PLANE, orow + lane,      o0);
        split_one_store2(g_Os, PLANE, orow + lane + 32, o1);
    } else {
        if (lane < 16) Arow[selj] = 1.0f;
    }
}

// ---------------------------------------------------------------------------
// Kernel 5: delta = O @ Wo^T + bo;  M_tilde = M + gate*delta (HMMA, 3 prod).
// ---------------------------------------------------------------------------
__global__ void __launch_bounds__(256) proj_kernel(
    const float* __restrict__ Mm, const float* __restrict__ bo,
    const float* __restrict__ gate, float* __restrict__ dout)
{
    extern __shared__ char sm[];
    int m0 = blockIdx.x << 7, n0 = blockIdx.y << 7;
    size_t aoff = (size_t)m0 * 512, boff = (size_t)n0 * 512;

    float acc[4][4][4];
#pragma unroll
    for (int a = 0; a < 4; a++)
#pragma unroll
        for (int b = 0; b < 4; b++)
#pragma unroll
            for (int c = 0; c < 4; c++) acc[a][b][c] = 0.f;

    gemm_tiles<3, 2>(g_Os + aoff, g_Os + PLANE + aoff, g_Os + 2 * PLANE + aoff,
                     g_Wos + boff, g_Wos + WPLANE + boff, g_Wos + 2 * WPLANE + boff,
                     32, sm, acc);

    int t = threadIdx.x, warp = t >> 5, lane = t & 31;
    int gq = lane >> 2, tq = lane & 3;
    int wm = (warp >> 2) << 6, wn = (warp & 3) << 5;
    float gg = gate[0];

#pragma unroll
    for (int mt = 0; mt < 4; mt++)
#pragma unroll
        for (int nt = 0; nt < 4; nt++) {
            int col = n0 + wn + nt * 8 + 2 * tq;
            float2 bv = *(const float2*)(bo + col);
#pragma unroll
            for (int hh = 0; hh < 2; hh++) {
                int row = m0 + wm + mt * 16 + gq + hh * 8;
                float2 mv = *(const float2*)(Mm + (size_t)row * 512 + col);
                *(float2*)(dout + (size_t)row * 512 + col) = make_float2(
                    mv.x + gg * (acc[mt][nt][2*hh]   + bv.x),
                    mv.y + gg * (acc[mt][nt][2*hh+1] + bv.y));
            }
        }
}

// ---------------------------------------------------------------------------
extern "C" void kernel_launch(void* const* d_in, const int* in_sizes, int n_in,
                              void* d_out, int out_size)
{
    const float* Mm   = (const float*)d_in[0];
    const float* Wq   = (const float*)d_in[1];
    const float* Wk   = (const float*)d_in[2];
    const float* Wv   = (const float*)d_in[3];
    const float* Wo   = (const float*)d_in[4];
    const float* bo   = (const float*)d_in[5];
    const float* gate = (const float*)d_in[6];
    float* out = (float*)d_out;

    // resolve device-symbol addresses (host-side, capture-safe)
    __nv_bfloat16 *pMs, *pWvs, *pWos;
    cudaGetSymbolAddress((void**)&pMs,  g_Ms);
    cudaGetSymbolAddress((void**)&pWvs, g_Wvs);
    cudaGetSymbolAddress((void**)&pWos, g_Wos);

    split2_kernel<<<8192, 256>>>(Mm, pMs, PLANE);
    split2_kernel<<<256, 256>>>(Wv, pWvs, WPLANE);
    split2_kernel<<<256, 256>>>(Wo, pWos, WPLANE);

    qk_kernel<<<dim3(256, 8, 2), 256>>>(Mm, Wq, Wk);
    vproj_kernel<<<dim3(128, 4), 256, 49152>>>();
    scores_kernel<<<dim3(8, 8, 128), 256, 49152>>>();
    attn_kernel<<<16384, 288>>>(out);
    proj_kernel<<<dim3(128, 4), 256, 49152>>>(Mm, bo, gate, out);
}